// round 10
// baseline (speedup 1.0000x reference)
#include <cuda_runtime.h>
#include <math.h>

#define NN     200000
#define EE     8192
#define HH     64
#define TEDIM  32
#define EADIM  32
#define G4     256     // 4H
#define DFEAT  128
#define KZ     192     // H + D_FEAT
#define AA     50
#define SCAN_BLOCKS 148
#define BDIM   512                        // 8 groups of 64
#define NGROUP 8
#define NSTREAM (SCAN_BLOCKS * NGROUP)    // 1184 batch streams
#define NBATCH (EE / 4)                   // 2048 4-event batches

// misc kernel roles: [0,64) zero done + build pairs ; [64,104) fuse
#define MISC_ZERO_BLOCKS 64
#define MISC_FUSE_BLOCKS 40
#define MISC_BLOCKS (MISC_ZERO_BLOCKS + MISC_FUSE_BLOCKS)

// ---------------- device scratch (static, no runtime alloc) ----------------
__device__ float g_h[(size_t)NN * HH];     // node memory (not pre-zeroed: seq==0 => 0)
__device__ float g_c[(size_t)NN * HH];     // LSTM cell state
__device__ int   g_done[NN];               // per-node completed-endpoint counter
__device__ int2  g_pairs[EE];              // (src, dst)
__device__ int   g_seq[2 * EE];            // per-endpoint rank among same-node endpoints
__device__ float g_Wf[KZ * AA];            // fused W_emb @ W_cls
__device__ float g_bf[AA];                 // fused bias

// ---------------- helpers ----------------
__device__ __forceinline__ int ld_acq(const int* p) {
    int v;
    asm volatile("ld.global.acquire.gpu.b32 %0, [%1];" : "=r"(v) : "l"(p));
    return v;
}
__device__ __forceinline__ void st_rel(int* p, int v) {
    asm volatile("st.global.release.gpu.b32 [%0], %1;" :: "l"(p), "r"(v) : "memory");
}
__device__ __forceinline__ void bar_group(int g) {
    asm volatile("bar.sync %0, 64;" :: "r"(g + 1) : "memory");
}
__device__ __forceinline__ float tanhx(float x) {   // HW tanh (sm_75+)
    float y;
    asm("tanh.approx.f32 %0, %1;" : "=f"(y) : "f"(x));
    return y;
}
__device__ __forceinline__ float sigf(float x) {    // sigmoid via HW tanh
    return fmaf(0.5f, tanhx(0.5f * x), 0.5f);
}

// ---------------- kernel 1: misc (zero done + pairs + fuse) — NO smem -----
__global__ void __launch_bounds__(256) misc_kernel(
    const int* __restrict__ eidx,
    const float* __restrict__ W_emb, const float* __restrict__ W_cls,
    const float* __restrict__ b_emb, const float* __restrict__ b_cls)
{
    int b = blockIdx.x;
    int t = threadIdx.x;
    if (b < MISC_ZERO_BLOCKS) {
        int n = b * 256 + t;              // endpoint id [0, 2*EE)
        int u = eidx[n];
        g_done[u] = 0;                    // racing same-value writes: benign
        if (n < EE) g_pairs[n] = make_int2(eidx[n], eidx[EE + n]);
    } else {
        int idx = (b - MISC_ZERO_BLOCKS) * 256 + t;
        if (idx < KZ * AA) {
            int k = idx / AA, a = idx % AA;
            float s = 0.f;
            #pragma unroll 8
            for (int c = 0; c < HH; c++) s = fmaf(W_emb[k * HH + c], W_cls[c * AA + a], s);
            g_Wf[idx] = s;
        } else if (idx < KZ * AA + AA) {
            int a = idx - KZ * AA;
            float s = b_cls[a];
            for (int c = 0; c < HH; c++) s = fmaf(b_emb[c], W_cls[c * AA + a], s);
            g_bf[a] = s;
        }
    }
}

// ---------------- kernel 2: seq — both endpoints of an event in one pass ---
__global__ void __launch_bounds__(256) seq_kernel(const int* __restrict__ eidx) {
    extern __shared__ int2 sp[];
    int t = threadIdx.x;
    for (int i = t; i < EE; i += 256)
        sp[i] = make_int2(eidx[i], eidx[EE + i]);
    __syncthreads();
    int lane = t & 31, w = t >> 5;
    for (int e = blockIdx.x * 8 + w; e < EE; e += gridDim.x * 8) {
        int2 pe = sp[e];
        int u0 = pe.x, u1 = pe.y;
        int c0 = 0, c1 = 0;
        for (int j = lane; j < e; j += 32) {
            int2 p = sp[j];
            c0 += (p.x == u0) + (p.y == u0);
            c1 += (p.x == u1) + (p.y == u1);
        }
        #pragma unroll
        for (int off = 16; off > 0; off >>= 1) {
            c0 += __shfl_down_sync(0xffffffffu, c0, off);
            c1 += __shfl_down_sync(0xffffffffu, c1, off);
        }
        if (lane == 0) {
            g_seq[2 * e] = c0;
            g_seq[2 * e + 1] = c1;
        }
    }
}

// ---------------- kernel 3: scan — 4-event batch per 64-thread group ------
// smem float offsets
#define O_WPM    0              // float2[64*64]: (w1+w2, w1-w2) per col
#define O_WC     8192           // float2[32*64]: comm weights, k-paired
#define O_WIH    12288          // permuted [k*64+col]*4+gate
#define O_WHH    28672
#define O_BMSG   45056
#define O_BLSTM  45120
#define O_TW     45376
#define O_TB     45408
#define O_GRP    45440
// group layout: pack float4[4][64] (1024 floats) | comm float[4][64] (256)
#define GRP_F    1280
#define SCAN_SMEM_F (O_GRP + NGROUP * GRP_F)   // 55680 floats = 222720 B

struct ScanCtx {
    const float2* sWpm;
    const float2* sWc;
    const float*  sWihP;
    const float*  sWhhP;
    const float*  sbmsg;
    const float*  sblstm;
    const float*  stw;
    const float*  stb;
    const float*  eattr;
    const float*  etime;
};

// single-event path (used only for rare conflicting batches)
__device__ __forceinline__ void process_one(
    int e, int lt, int g, float* grp, const ScanCtx& cx)
{
    float2* sHp = (float2*)grp;
    float2* sSD = (float2*)(grp + 128);
    float*  sCm = grp + 256;
    float2* sMp = (float2*)(grp + 320);

    int2 pr = g_pairs[e];
    int s0 = g_seq[2 * e], s1 = g_seq[2 * e + 1];
    bool w0 = (s0 > 0), w1 = (s1 > 0);
    if (w0 || w1) {
        int guard = 0;
        while (((w0 && ld_acq(&g_done[pr.x]) != s0) ||
                (w1 && ld_acq(&g_done[pr.y]) != s1)) && ++guard < (1 << 18)) {}
    }
    float hs = w0 ? __ldcg(&g_h[(size_t)pr.x * HH + lt]) : 0.f;
    float cs = w0 ? __ldcg(&g_c[(size_t)pr.x * HH + lt]) : 0.f;
    float hd = w1 ? __ldcg(&g_h[(size_t)pr.y * HH + lt]) : 0.f;
    float cd = w1 ? __ldcg(&g_c[(size_t)pr.y * HH + lt]) : 0.f;
    sHp[lt] = make_float2(hs, hd);
    sSD[lt] = make_float2(hs + hd, hs - hd);
    sCm[lt] = (lt < EADIM) ? cx.eattr[e * EADIM + lt]
            : cosf(__ldg(&cx.etime[e]) * cx.stw[lt - EADIM] + cx.stb[lt - EADIM]);
    bar_group(g);

    float u = 0.f, v = 0.f, ac = cx.sbmsg[lt];
    #pragma unroll 8
    for (int k = 0; k < 64; k++) {
        float2 sd = sSD[k];
        float2 w  = cx.sWpm[k * 64 + lt];
        u = fmaf(sd.x, w.x, u);
        v = fmaf(sd.y, w.y, v);
    }
    const float2* cm2 = (const float2*)sCm;
    #pragma unroll 8
    for (int k2 = 0; k2 < 32; k2++) {
        float2 c = cm2[k2];
        float2 w = cx.sWc[k2 * 64 + lt];
        ac = fmaf(c.x, w.x, ac);
        ac = fmaf(c.y, w.y, ac);
    }
    sMp[lt] = make_float2(fmaxf(ac + 0.5f * (u - v), 0.f),
                          fmaxf(ac + 0.5f * (u + v), 0.f));
    bar_group(g);

    float a00 = cx.sblstm[lt],       a01 = cx.sblstm[lt + 64];
    float a02 = cx.sblstm[lt + 128], a03 = cx.sblstm[lt + 192];
    float a10 = a00, a11 = a01, a12 = a02, a13 = a03;
    #pragma unroll 8
    for (int k = 0; k < 64; k++) {
        float2 m = sMp[k];
        float2 h = sHp[k];
        float4 wi = *(const float4*)&cx.sWihP[(k * 64 + lt) * 4];
        float4 wh = *(const float4*)&cx.sWhhP[(k * 64 + lt) * 4];
        a00 = fmaf(m.x, wi.x, a00); a01 = fmaf(m.x, wi.y, a01);
        a02 = fmaf(m.x, wi.z, a02); a03 = fmaf(m.x, wi.w, a03);
        a10 = fmaf(m.y, wi.x, a10); a11 = fmaf(m.y, wi.y, a11);
        a12 = fmaf(m.y, wi.z, a12); a13 = fmaf(m.y, wi.w, a13);
        a00 = fmaf(h.x, wh.x, a00); a01 = fmaf(h.x, wh.y, a01);
        a02 = fmaf(h.x, wh.z, a02); a03 = fmaf(h.x, wh.w, a03);
        a10 = fmaf(h.y, wh.x, a10); a11 = fmaf(h.y, wh.y, a11);
        a12 = fmaf(h.y, wh.z, a12); a13 = fmaf(h.y, wh.w, a13);
    }
    bool selfloop = (pr.x == pr.y);
    {
        float cn = sigf(a11) * cd + sigf(a10) * tanhx(a12);
        float hn = sigf(a13) * tanhx(cn);
        __stcg(&g_h[(size_t)pr.y * HH + lt], hn);
        __stcg(&g_c[(size_t)pr.y * HH + lt], cn);
    }
    if (!selfloop) {
        float cn = sigf(a01) * cs + sigf(a00) * tanhx(a02);
        float hn = sigf(a03) * tanhx(cn);
        __stcg(&g_h[(size_t)pr.x * HH + lt], hn);
        __stcg(&g_c[(size_t)pr.x * HH + lt], cn);
    }
    bar_group(g);
    if (lt == 0) {
        __threadfence();
        if (selfloop) {
            st_rel(&g_done[pr.x], s0 + 2);
        } else {
            st_rel(&g_done[pr.x], s0 + 1);
            st_rel(&g_done[pr.y], s1 + 1);
        }
    }
    bar_group(g);
}

__global__ void __launch_bounds__(BDIM, 1) scan_kernel(
    const float* __restrict__ Wmsg, const float* __restrict__ bmsg,
    const float* __restrict__ Wih,  const float* __restrict__ Whh,
    const float* __restrict__ blstm, const float* __restrict__ tw,
    const float* __restrict__ tb,   const float* __restrict__ eattr,
    const float* __restrict__ etime)
{
    extern __shared__ float sm[];
    int t = threadIdx.x;
    int g = t >> 6, lt = t & 63;

    ScanCtx cx;
    cx.sWpm  = (const float2*)(sm + O_WPM);
    cx.sWc   = (const float2*)(sm + O_WC);
    cx.sWihP = sm + O_WIH;
    cx.sWhhP = sm + O_WHH;
    cx.sbmsg = sm + O_BMSG;
    cx.sblstm= sm + O_BLSTM;
    cx.stw   = sm + O_TW;
    cx.stb   = sm + O_TB;
    cx.eattr = eattr;
    cx.etime = etime;

    float*  grp = sm + O_GRP + g * GRP_F;
    float4* pk  = (float4*)grp;          // [4][64] (phase1: sd.x,sd.y,hs,hd ; phase2: m0,m1,hs,hd)
    float*  cm  = grp + 1024;            // [4][64]

    // ---- load + transform weights (whole block) ----
    {
        float2* wWpm = (float2*)(sm + O_WPM);
        float2* wWc  = (float2*)(sm + O_WC);
        float*  wIh  = sm + O_WIH;
        float*  wHh  = sm + O_WHH;
        for (int i = t; i < 64 * 64; i += BDIM) {
            int k = i >> 6, col = i & 63;
            float w1 = Wmsg[k * HH + col];
            float w2 = Wmsg[(64 + k) * HH + col];
            wWpm[i] = make_float2(w1 + w2, w1 - w2);
        }
        for (int i = t; i < 32 * 64; i += BDIM) {
            int k2 = i >> 6, col = i & 63;
            wWc[i] = make_float2(Wmsg[(128 + 2 * k2) * HH + col],
                                 Wmsg[(129 + 2 * k2) * HH + col]);
        }
        for (int i = t; i < HH * G4; i += BDIM) {
            int k = i >> 8, j = i & 255;
            int p = ((k << 6) + (j & 63)) * 4 + (j >> 6);
            wIh[p] = Wih[i];
            wHh[p] = Whh[i];
        }
        if (t < HH)    (sm + O_BMSG)[t]  = bmsg[t];
        if (t < G4)    (sm + O_BLSTM)[t] = blstm[t];
        if (t < TEDIM) { (sm + O_TW)[t] = tw[t]; (sm + O_TB)[t] = tb[t]; }
    }
    __syncthreads();

    for (int p = blockIdx.x * NGROUP + g; p < NBATCH; p += NSTREAM) {
        int e0 = 4 * p;
        int2 pr[4];
        #pragma unroll
        for (int E = 0; E < 4; E++) pr[E] = g_pairs[e0 + E];

        // cross-event conflict check (intra-event self-loop is fine)
        bool conflict = false;
        #pragma unroll
        for (int a = 0; a < 4; a++)
            #pragma unroll
            for (int b2 = a + 1; b2 < 4; b2++)
                conflict |= (pr[a].x == pr[b2].x) | (pr[a].x == pr[b2].y) |
                            (pr[a].y == pr[b2].x) | (pr[a].y == pr[b2].y);
        if (conflict) {
            #pragma unroll
            for (int E = 0; E < 4; E++) process_one(e0 + E, lt, g, grp, cx);
            continue;
        }

        int s0[4], s1[4];
        bool w0[4], w1[4];
        bool need = false;
        #pragma unroll
        for (int E = 0; E < 4; E++) {
            s0[E] = g_seq[2 * (e0 + E)];
            s1[E] = g_seq[2 * (e0 + E) + 1];
            w0[E] = (s0[E] > 0); w1[E] = (s1[E] > 0);
            need |= w0[E] | w1[E];
        }
        if (need) {
            int guard = 0;
            while (guard < (1 << 18)) {
                bool ok = true;
                #pragma unroll
                for (int E = 0; E < 4; E++) {
                    ok &= (!w0[E] || ld_acq(&g_done[pr[E].x]) == s0[E]);
                    ok &= (!w1[E] || ld_acq(&g_done[pr[E].y]) == s1[E]);
                }
                if (ok) break;
                guard++;
            }
        }

        // ---- states (16 concurrent loads) + pack init + comm ----
        float hs[4], hd[4], cs[4], cd[4];
        #pragma unroll
        for (int E = 0; E < 4; E++) {
            hs[E] = w0[E] ? __ldcg(&g_h[(size_t)pr[E].x * HH + lt]) : 0.f;
            cs[E] = w0[E] ? __ldcg(&g_c[(size_t)pr[E].x * HH + lt]) : 0.f;
            hd[E] = w1[E] ? __ldcg(&g_h[(size_t)pr[E].y * HH + lt]) : 0.f;
            cd[E] = w1[E] ? __ldcg(&g_c[(size_t)pr[E].y * HH + lt]) : 0.f;
        }
        #pragma unroll
        for (int E = 0; E < 4; E++)
            pk[E * 64 + lt] = make_float4(hs[E] + hd[E], hs[E] - hd[E], hs[E], hd[E]);
        #pragma unroll
        for (int E = 0; E < 4; E++) {
            if (lt < EADIM) {
                cm[E * 64 + lt] = eattr[(e0 + E) * EADIM + lt];
            } else {
                int i = lt - EADIM;
                cm[E * 64 + lt] = cosf(__ldg(&etime[e0 + E]) * cx.stw[i] + cx.stb[i]);
            }
        }
        bar_group(g);

        // ---- gemm1: 4 events share each weight read ----
        float u[4] = {0.f, 0.f, 0.f, 0.f}, v[4] = {0.f, 0.f, 0.f, 0.f};
        float acg[4];
        float bm = cx.sbmsg[lt];
        #pragma unroll
        for (int E = 0; E < 4; E++) acg[E] = bm;
        #pragma unroll 4
        for (int k = 0; k < 64; k++) {
            float2 w = cx.sWpm[k * 64 + lt];
            #pragma unroll
            for (int E = 0; E < 4; E++) {
                float4 f = pk[E * 64 + k];
                u[E] = fmaf(f.x, w.x, u[E]);
                v[E] = fmaf(f.y, w.y, v[E]);
            }
        }
        #pragma unroll 4
        for (int k2 = 0; k2 < 32; k2++) {
            float2 w = cx.sWc[k2 * 64 + lt];
            #pragma unroll
            for (int E = 0; E < 4; E++) {
                float2 c = ((const float2*)(cm + E * 64))[k2];
                acg[E] = fmaf(c.x, w.x, acg[E]);
                acg[E] = fmaf(c.y, w.y, acg[E]);
            }
        }
        bar_group(g);   // all gemm1 reads of pk done before overwrite

        #pragma unroll
        for (int E = 0; E < 4; E++) {
            float m0 = fmaxf(acg[E] + 0.5f * (u[E] - v[E]), 0.f);  // src row
            float m1 = fmaxf(acg[E] + 0.5f * (u[E] + v[E]), 0.f);  // dst row
            pk[E * 64 + lt] = make_float4(m0, m1, hs[E], hd[E]);
        }
        bar_group(g);

        // ---- gemm2: 4 events share each weight read (32 accumulators) ----
        float bl0 = cx.sblstm[lt],       bl1 = cx.sblstm[lt + 64];
        float bl2 = cx.sblstm[lt + 128], bl3 = cx.sblstm[lt + 192];
        float acc[4][8];
        #pragma unroll
        for (int E = 0; E < 4; E++) {
            acc[E][0] = bl0; acc[E][1] = bl1; acc[E][2] = bl2; acc[E][3] = bl3;
            acc[E][4] = bl0; acc[E][5] = bl1; acc[E][6] = bl2; acc[E][7] = bl3;
        }
        #pragma unroll 2
        for (int k = 0; k < 64; k++) {
            float4 wi = *(const float4*)&cx.sWihP[(k * 64 + lt) * 4];
            float4 wh = *(const float4*)&cx.sWhhP[(k * 64 + lt) * 4];
            #pragma unroll
            for (int E = 0; E < 4; E++) {
                float4 f = pk[E * 64 + k];       // (m0, m1, hs, hd)
                acc[E][0] = fmaf(f.x, wi.x, acc[E][0]);
                acc[E][1] = fmaf(f.x, wi.y, acc[E][1]);
                acc[E][2] = fmaf(f.x, wi.z, acc[E][2]);
                acc[E][3] = fmaf(f.x, wi.w, acc[E][3]);
                acc[E][0] = fmaf(f.z, wh.x, acc[E][0]);
                acc[E][1] = fmaf(f.z, wh.y, acc[E][1]);
                acc[E][2] = fmaf(f.z, wh.z, acc[E][2]);
                acc[E][3] = fmaf(f.z, wh.w, acc[E][3]);
                acc[E][4] = fmaf(f.y, wi.x, acc[E][4]);
                acc[E][5] = fmaf(f.y, wi.y, acc[E][5]);
                acc[E][6] = fmaf(f.y, wi.z, acc[E][6]);
                acc[E][7] = fmaf(f.y, wi.w, acc[E][7]);
                acc[E][4] = fmaf(f.w, wh.x, acc[E][4]);
                acc[E][5] = fmaf(f.w, wh.y, acc[E][5]);
                acc[E][6] = fmaf(f.w, wh.z, acc[E][6]);
                acc[E][7] = fmaf(f.w, wh.w, acc[E][7]);
            }
        }

        // ---- elementwise + stores (dst row wins on per-event self-loop) ----
        #pragma unroll
        for (int E = 0; E < 4; E++) {
            bool sl = (pr[E].x == pr[E].y);
            {   // dst row
                float cn = sigf(acc[E][5]) * cd[E] + sigf(acc[E][4]) * tanhx(acc[E][6]);
                float hn = sigf(acc[E][7]) * tanhx(cn);
                __stcg(&g_h[(size_t)pr[E].y * HH + lt], hn);
                __stcg(&g_c[(size_t)pr[E].y * HH + lt], cn);
            }
            if (!sl) {  // src row
                float cn = sigf(acc[E][1]) * cs[E] + sigf(acc[E][0]) * tanhx(acc[E][2]);
                float hn = sigf(acc[E][3]) * tanhx(cn);
                __stcg(&g_h[(size_t)pr[E].x * HH + lt], hn);
                __stcg(&g_c[(size_t)pr[E].x * HH + lt], cn);
            }
        }
        bar_group(g);

        if (lt == 0) {
            __threadfence();
            #pragma unroll
            for (int E = 0; E < 4; E++) {
                if (pr[E].x == pr[E].y) {
                    st_rel(&g_done[pr[E].x], s0[E] + 2);
                } else {
                    st_rel(&g_done[pr[E].x], s0[E] + 1);
                    st_rel(&g_done[pr[E].y], s1[E] + 1);
                }
            }
        }
        bar_group(g);
    }
}

// ---------------- kernel 4: epilogue — 128-thr blocks, 4 events/warp -------
// dyn smem layout (floats): sWf[KZ*AA] | sbf[64] | sCat[4][4][KZ]
#define EP_O_WF   0
#define EP_O_BF   (KZ * AA)                 // 9600
#define EP_O_CAT  (EP_O_BF + 64)            // 9664
#define EP_SMEM_F (EP_O_CAT + 4 * 4 * KZ)   // 12736 floats

__global__ void __launch_bounds__(128) epilogue_kernel(const float* __restrict__ x,
                                                       const int* __restrict__ eidx,
                                                       float* __restrict__ out) {
    extern __shared__ float esm[];
    float* sWf = esm + EP_O_WF;
    float* sbf = esm + EP_O_BF;
    int t = threadIdx.x;
    for (int i = t; i < KZ * AA; i += 128) sWf[i] = g_Wf[i];
    if (t < AA) sbf[t] = g_bf[t];
    __syncthreads();
    int lane = t & 31, w = t >> 5;
    float* sc = esm + EP_O_CAT + w * 4 * KZ;
    int e0 = (blockIdx.x * 4 + w) * 4;        // 4 events per warp
    #pragma unroll
    for (int j = 0; j < 4; j++) {
        int d = eidx[EE + e0 + j];
        const float* hv = &g_h[(size_t)d * HH];
        const float* xv = &x[(size_t)d * DFEAT];
        #pragma unroll
        for (int q = 0; q < 6; q++) {
            int k = lane + q * 32;
            sc[j * KZ + k] = (k < HH) ? hv[k] : xv[k - HH];
        }
    }
    __syncwarp();
    bool hi = (lane < AA - 32);
    float b0 = sbf[lane], b1 = hi ? sbf[lane + 32] : 0.f;
    float a00 = b0, a01 = b1, a10 = b0, a11 = b1;
    float a20 = b0, a21 = b1, a30 = b0, a31 = b1;
    for (int k4 = 0; k4 < KZ; k4 += 4) {
        float4 v0 = *(const float4*)&sc[0 * KZ + k4];
        float4 v1 = *(const float4*)&sc[1 * KZ + k4];
        float4 v2 = *(const float4*)&sc[2 * KZ + k4];
        float4 v3 = *(const float4*)&sc[3 * KZ + k4];
        #pragma unroll
        for (int i = 0; i < 4; i++) {
            float wA = sWf[(k4 + i) * AA + lane];
            float wB = hi ? sWf[(k4 + i) * AA + lane + 32] : 0.f;
            float e0v = (&v0.x)[i], e1v = (&v1.x)[i];
            float e2v = (&v2.x)[i], e3v = (&v3.x)[i];
            a00 = fmaf(e0v, wA, a00); a01 = fmaf(e0v, wB, a01);
            a10 = fmaf(e1v, wA, a10); a11 = fmaf(e1v, wB, a11);
            a20 = fmaf(e2v, wA, a20); a21 = fmaf(e2v, wB, a21);
            a30 = fmaf(e3v, wA, a30); a31 = fmaf(e3v, wB, a31);
        }
    }
    out[(size_t)(e0 + 0) * AA + lane] = a00;
    out[(size_t)(e0 + 1) * AA + lane] = a10;
    out[(size_t)(e0 + 2) * AA + lane] = a20;
    out[(size_t)(e0 + 3) * AA + lane] = a30;
    if (hi) {
        out[(size_t)(e0 + 0) * AA + lane + 32] = a01;
        out[(size_t)(e0 + 1) * AA + lane + 32] = a11;
        out[(size_t)(e0 + 2) * AA + lane + 32] = a21;
        out[(size_t)(e0 + 3) * AA + lane + 32] = a31;
    }
}

// ---------------- launch ----------------
extern "C" void kernel_launch(void* const* d_in, const int* in_sizes, int n_in,
                              void* d_out, int out_size) {
    const float* x      = (const float*)d_in[0];
    const int*   eidx   = (const int*)  d_in[1];
    const float* eattr  = (const float*)d_in[2];
    const float* etime  = (const float*)d_in[3];
    const float* time_w = (const float*)d_in[4];
    const float* time_b = (const float*)d_in[5];
    const float* W_msg  = (const float*)d_in[6];
    const float* b_msg  = (const float*)d_in[7];
    const float* W_ih   = (const float*)d_in[8];
    const float* W_hh   = (const float*)d_in[9];
    const float* b_lstm = (const float*)d_in[10];
    const float* W_emb  = (const float*)d_in[11];
    const float* b_emb  = (const float*)d_in[12];
    const float* W_cls  = (const float*)d_in[13];
    const float* b_cls  = (const float*)d_in[14];
    float* out = (float*)d_out;

    cudaFuncSetAttribute(seq_kernel, cudaFuncAttributeMaxDynamicSharedMemorySize,
                         EE * (int)sizeof(int2));
    cudaFuncSetAttribute(scan_kernel, cudaFuncAttributeMaxDynamicSharedMemorySize,
                         SCAN_SMEM_F * (int)sizeof(float));
    cudaFuncSetAttribute(epilogue_kernel, cudaFuncAttributeMaxDynamicSharedMemorySize,
                         EP_SMEM_F * (int)sizeof(float));

    misc_kernel<<<MISC_BLOCKS, 256>>>(eidx, W_emb, W_cls, b_emb, b_cls);
    seq_kernel<<<256, 256, EE * sizeof(int2)>>>(eidx);
    scan_kernel<<<SCAN_BLOCKS, BDIM, SCAN_SMEM_F * sizeof(float)>>>(
        W_msg, b_msg, W_ih, W_hh, b_lstm, time_w, time_b, eattr, etime);
    epilogue_kernel<<<512, 128, EP_SMEM_F * sizeof(float)>>>(x, eidx, out);
}

// round 11
// speedup vs baseline: 1.0688x; 1.0688x over previous
#include <cuda_runtime.h>
#include <math.h>

#define NN     200000
#define EE     8192
#define HH     64
#define TEDIM  32
#define EADIM  32
#define G4     256     // 4H
#define DFEAT  128
#define KZ     192     // H + D_FEAT
#define AA     50
#define SCAN_BLOCKS 148
#define BDIM   640                        // 20 warps
#define NGROUP 10                         // 64-thread groups
#define NSTREAM (SCAN_BLOCKS * NGROUP)    // 1480 pair streams

#define MISC_BLOCKS 40                    // fuse role only

// ---------------- device scratch (static, no runtime alloc) ----------------
__device__ float g_h[(size_t)NN * HH];     // node memory (not pre-zeroed: seq==0 => 0)
__device__ float g_c[(size_t)NN * HH];     // LSTM cell state
__device__ int   g_done[NN];               // per-node completed-endpoint counter
__device__ int2  g_pairs[EE];              // (src, dst)
__device__ int   g_seq[2 * EE];            // per-endpoint rank among same-node endpoints
__device__ float g_Wf[KZ * AA];            // fused W_emb @ W_cls
__device__ float g_bf[AA];                 // fused bias
__device__ int   g_sync;                   // grid barrier counter (reset by misc)

// ---------------- helpers ----------------
__device__ __forceinline__ int ld_acq(const int* p) {
    int v;
    asm volatile("ld.global.acquire.gpu.b32 %0, [%1];" : "=r"(v) : "l"(p));
    return v;
}
__device__ __forceinline__ void st_rel(int* p, int v) {
    asm volatile("st.global.release.gpu.b32 [%0], %1;" :: "l"(p), "r"(v) : "memory");
}
__device__ __forceinline__ void bar_group(int g) {
    asm volatile("bar.sync %0, 64;" :: "r"(g + 1) : "memory");
}
__device__ __forceinline__ float tanhx(float x) {   // HW tanh (sm_75+)
    float y;
    asm("tanh.approx.f32 %0, %1;" : "=f"(y) : "f"(x));
    return y;
}
__device__ __forceinline__ float sigf(float x) {    // sigmoid via HW tanh
    return fmaf(0.5f, tanhx(0.5f * x), 0.5f);
}

// ---------------- kernel 1: misc (fuse + sync reset) — NO smem ------------
__global__ void __launch_bounds__(256) misc_kernel(
    const float* __restrict__ W_emb, const float* __restrict__ W_cls,
    const float* __restrict__ b_emb, const float* __restrict__ b_cls)
{
    int idx = blockIdx.x * 256 + threadIdx.x;
    if (idx == 0) g_sync = 0;
    if (idx < KZ * AA) {
        int k = idx / AA, a = idx % AA;
        float s = 0.f;
        #pragma unroll 8
        for (int c = 0; c < HH; c++) s = fmaf(W_emb[k * HH + c], W_cls[c * AA + a], s);
        g_Wf[idx] = s;
    } else if (idx < KZ * AA + AA) {
        int a = idx - KZ * AA;
        float s = b_cls[a];
        for (int c = 0; c < HH; c++) s = fmaf(b_emb[c], W_cls[c * AA + a], s);
        g_bf[a] = s;
    }
}

// ---------------- kernel 2: scan (prologue: pairs+done+seq; grid barrier) --
// smem float offsets (weights overwrite the prologue's sp region)
#define O_WPM    0              // float2[64*64]: (w1+w2, w1-w2) per col
#define O_WC     8192           // float2[32*64]: comm weights, k-paired
#define O_WIH    12288          // permuted [k*64+col]*4+gate
#define O_WHH    28672
#define O_BMSG   45056
#define O_BLSTM  45120
#define O_TW     45376
#define O_TB     45408
#define O_GRP    45440
// group layout: HpA(128) HpB(128) SDA(128) SDB(128) CommA(64) CommB(64) MpA(128) MpB(128)
#define GRP_F    896
#define SCAN_SMEM_F (O_GRP + NGROUP * GRP_F)   // 54400 floats = 212.5 KB

struct ScanCtx {
    const float2* sWpm;
    const float2* sWc;
    const float*  sWihP;
    const float*  sWhhP;
    const float*  sbmsg;
    const float*  sblstm;
    const float*  stw;
    const float*  stb;
    const float*  eattr;
    const float*  etime;
};

// single-event path (used only for rare conflicting pairs)
__device__ __forceinline__ void process_one(
    int e, int lt, int g,
    float2* sHp, float2* sSD, float* sComm, float2* sMp, const ScanCtx& cx)
{
    int2 pr = g_pairs[e];
    int s0 = g_seq[2 * e], s1 = g_seq[2 * e + 1];
    bool w0 = (s0 > 0), w1 = (s1 > 0);
    if (w0 || w1) {
        int guard = 0;
        while (((w0 && ld_acq(&g_done[pr.x]) != s0) ||
                (w1 && ld_acq(&g_done[pr.y]) != s1)) && ++guard < (1 << 18)) {}
    }
    float hs = w0 ? __ldcg(&g_h[(size_t)pr.x * HH + lt]) : 0.f;
    float cs = w0 ? __ldcg(&g_c[(size_t)pr.x * HH + lt]) : 0.f;
    float hd = w1 ? __ldcg(&g_h[(size_t)pr.y * HH + lt]) : 0.f;
    float cd = w1 ? __ldcg(&g_c[(size_t)pr.y * HH + lt]) : 0.f;
    sHp[lt] = make_float2(hs, hd);
    sSD[lt] = make_float2(hs + hd, hs - hd);
    sComm[lt] = (lt < EADIM) ? cx.eattr[e * EADIM + lt]
              : cosf(__ldg(&cx.etime[e]) * cx.stw[lt - EADIM] + cx.stb[lt - EADIM]);
    bar_group(g);

    float u = 0.f, v = 0.f, ac = cx.sbmsg[lt];
    #pragma unroll 8
    for (int k = 0; k < 64; k++) {
        float2 sd = sSD[k];
        float2 w  = cx.sWpm[k * 64 + lt];
        u = fmaf(sd.x, w.x, u);
        v = fmaf(sd.y, w.y, v);
    }
    const float2* cm2 = (const float2*)sComm;
    #pragma unroll 8
    for (int k2 = 0; k2 < 32; k2++) {
        float2 c = cm2[k2];
        float2 w = cx.sWc[k2 * 64 + lt];
        ac = fmaf(c.x, w.x, ac);
        ac = fmaf(c.y, w.y, ac);
    }
    sMp[lt] = make_float2(fmaxf(ac + 0.5f * (u - v), 0.f),
                          fmaxf(ac + 0.5f * (u + v), 0.f));
    bar_group(g);

    float a00 = cx.sblstm[lt],       a01 = cx.sblstm[lt + 64];
    float a02 = cx.sblstm[lt + 128], a03 = cx.sblstm[lt + 192];
    float a10 = a00, a11 = a01, a12 = a02, a13 = a03;
    #pragma unroll 8
    for (int k = 0; k < 64; k++) {
        float2 m = sMp[k];
        float2 h = sHp[k];
        float4 wi = *(const float4*)&cx.sWihP[(k * 64 + lt) * 4];
        float4 wh = *(const float4*)&cx.sWhhP[(k * 64 + lt) * 4];
        a00 = fmaf(m.x, wi.x, a00); a01 = fmaf(m.x, wi.y, a01);
        a02 = fmaf(m.x, wi.z, a02); a03 = fmaf(m.x, wi.w, a03);
        a10 = fmaf(m.y, wi.x, a10); a11 = fmaf(m.y, wi.y, a11);
        a12 = fmaf(m.y, wi.z, a12); a13 = fmaf(m.y, wi.w, a13);
        a00 = fmaf(h.x, wh.x, a00); a01 = fmaf(h.x, wh.y, a01);
        a02 = fmaf(h.x, wh.z, a02); a03 = fmaf(h.x, wh.w, a03);
        a10 = fmaf(h.y, wh.x, a10); a11 = fmaf(h.y, wh.y, a11);
        a12 = fmaf(h.y, wh.z, a12); a13 = fmaf(h.y, wh.w, a13);
    }
    bool selfloop = (pr.x == pr.y);
    {
        float cn = sigf(a11) * cd + sigf(a10) * tanhx(a12);
        float hn = sigf(a13) * tanhx(cn);
        __stcg(&g_h[(size_t)pr.y * HH + lt], hn);
        __stcg(&g_c[(size_t)pr.y * HH + lt], cn);
    }
    if (!selfloop) {
        float cn = sigf(a01) * cs + sigf(a00) * tanhx(a02);
        float hn = sigf(a03) * tanhx(cn);
        __stcg(&g_h[(size_t)pr.x * HH + lt], hn);
        __stcg(&g_c[(size_t)pr.x * HH + lt], cn);
    }
    bar_group(g);
    if (lt == 0) {
        __threadfence();
        if (selfloop) {
            st_rel(&g_done[pr.x], s0 + 2);
        } else {
            st_rel(&g_done[pr.x], s0 + 1);
            st_rel(&g_done[pr.y], s1 + 1);
        }
    }
    bar_group(g);
}

__global__ void __launch_bounds__(BDIM, 1) scan_kernel(
    const int* __restrict__ eidx,
    const float* __restrict__ Wmsg, const float* __restrict__ bmsg,
    const float* __restrict__ Wih,  const float* __restrict__ Whh,
    const float* __restrict__ blstm, const float* __restrict__ tw,
    const float* __restrict__ tb,   const float* __restrict__ eattr,
    const float* __restrict__ etime)
{
    extern __shared__ float sm[];
    int t = threadIdx.x;
    int g = t >> 6, lt = t & 63;

    // ================= PROLOGUE A: pairs + done-zero + seq =================
    {
        int2* sp = (int2*)sm;                      // 64 KB, overwritten later
        for (int i = t; i < EE; i += BDIM)
            sp[i] = make_int2(eidx[i], eidx[EE + i]);
        __syncthreads();

        // zero done counters + publish pairs (disjoint global slices)
        for (int n = blockIdx.x * BDIM + t; n < 2 * EE; n += SCAN_BLOCKS * BDIM)
            g_done[eidx[n]] = 0;
        for (int i = blockIdx.x * BDIM + t; i < EE; i += SCAN_BLOCKS * BDIM)
            g_pairs[i] = sp[i];

        // seq: one warp per event, counting earlier same-node endpoints
        int lane = t & 31, w = t >> 5;
        for (int e = blockIdx.x * 20 + w; e < EE; e += SCAN_BLOCKS * 20) {
            int2 pe = sp[e];
            int c0 = 0, c1 = 0;
            for (int j = lane; j < e; j += 32) {
                int2 p = sp[j];
                c0 += (p.x == pe.x) + (p.y == pe.x);
                c1 += (p.x == pe.y) + (p.y == pe.y);
            }
            #pragma unroll
            for (int off = 16; off > 0; off >>= 1) {
                c0 += __shfl_down_sync(0xffffffffu, c0, off);
                c1 += __shfl_down_sync(0xffffffffu, c1, off);
            }
            if (lane == 0) {
                g_seq[2 * e] = c0;
                g_seq[2 * e + 1] = c1;
            }
        }
        __syncthreads();

        // grid barrier (all 148 blocks co-resident: 1 block/SM persistent)
        if (t == 0) {
            __threadfence();
            atomicAdd(&g_sync, 1);
            int guard = 0;
            while (ld_acq(&g_sync) != SCAN_BLOCKS && ++guard < (1 << 22)) {}
        }
        __syncthreads();
    }

    // ================= PROLOGUE B: weights into smem ======================
    ScanCtx cx;
    cx.sWpm  = (const float2*)(sm + O_WPM);
    cx.sWc   = (const float2*)(sm + O_WC);
    cx.sWihP = sm + O_WIH;
    cx.sWhhP = sm + O_WHH;
    cx.sbmsg = sm + O_BMSG;
    cx.sblstm= sm + O_BLSTM;
    cx.stw   = sm + O_TW;
    cx.stb   = sm + O_TB;
    cx.eattr = eattr;
    cx.etime = etime;

    float* grp = sm + O_GRP + g * GRP_F;
    float2* sHpA   = (float2*)grp;
    float2* sHpB   = (float2*)(grp + 128);
    float2* sSDA   = (float2*)(grp + 256);
    float2* sSDB   = (float2*)(grp + 384);
    float*  sCommA = grp + 512;
    float*  sCommB = grp + 576;
    float2* sMpA   = (float2*)(grp + 640);
    float2* sMpB   = (float2*)(grp + 768);

    {
        float2* wWpm = (float2*)(sm + O_WPM);
        float2* wWc  = (float2*)(sm + O_WC);
        float*  wIh  = sm + O_WIH;
        float*  wHh  = sm + O_WHH;
        for (int i = t; i < 64 * 64; i += BDIM) {
            int k = i >> 6, col = i & 63;
            float w1 = Wmsg[k * HH + col];
            float w2 = Wmsg[(64 + k) * HH + col];
            wWpm[i] = make_float2(w1 + w2, w1 - w2);
        }
        for (int i = t; i < 32 * 64; i += BDIM) {
            int k2 = i >> 6, col = i & 63;
            wWc[i] = make_float2(Wmsg[(128 + 2 * k2) * HH + col],
                                 Wmsg[(129 + 2 * k2) * HH + col]);
        }
        for (int i = t; i < HH * G4; i += BDIM) {
            int k = i >> 8, j = i & 255;
            int p = ((k << 6) + (j & 63)) * 4 + (j >> 6);
            wIh[p] = Wih[i];
            wHh[p] = Whh[i];
        }
        if (t < HH)    (sm + O_BMSG)[t]  = bmsg[t];
        if (t < G4)    (sm + O_BLSTM)[t] = blstm[t];
        if (t < TEDIM) { (sm + O_TW)[t] = tw[t]; (sm + O_TB)[t] = tb[t]; }
    }
    __syncthreads();

    // ================= MAIN LOOP: pair-of-events per group (R9) ===========
    for (int p = blockIdx.x * NGROUP + g; p < EE / 2; p += NSTREAM) {
        int eA = 2 * p, eB = 2 * p + 1;
        int2 prA = g_pairs[eA], prB = g_pairs[eB];

        bool conflict = (prA.x == prB.x) | (prA.x == prB.y) |
                        (prA.y == prB.x) | (prA.y == prB.y);
        if (conflict) {    // rare: process sequentially
            process_one(eA, lt, g, sHpA, sSDA, sCommA, sMpA, cx);
            process_one(eB, lt, g, sHpA, sSDA, sCommA, sMpA, cx);
            continue;
        }

        int s0A = g_seq[2 * eA], s1A = g_seq[2 * eA + 1];
        int s0B = g_seq[2 * eB], s1B = g_seq[2 * eB + 1];
        bool wA0 = (s0A > 0), wA1 = (s1A > 0), wB0 = (s0B > 0), wB1 = (s1B > 0);
        if (wA0 | wA1 | wB0 | wB1) {
            int guard = 0;
            while (((wA0 && ld_acq(&g_done[prA.x]) != s0A) ||
                    (wA1 && ld_acq(&g_done[prA.y]) != s1A) ||
                    (wB0 && ld_acq(&g_done[prB.x]) != s0B) ||
                    (wB1 && ld_acq(&g_done[prB.y]) != s1B)) && ++guard < (1 << 18)) {}
        }

        // ---- states + comm for both events ----
        float hsA = wA0 ? __ldcg(&g_h[(size_t)prA.x * HH + lt]) : 0.f;
        float csA = wA0 ? __ldcg(&g_c[(size_t)prA.x * HH + lt]) : 0.f;
        float hdA = wA1 ? __ldcg(&g_h[(size_t)prA.y * HH + lt]) : 0.f;
        float cdA = wA1 ? __ldcg(&g_c[(size_t)prA.y * HH + lt]) : 0.f;
        float hsB = wB0 ? __ldcg(&g_h[(size_t)prB.x * HH + lt]) : 0.f;
        float csB = wB0 ? __ldcg(&g_c[(size_t)prB.x * HH + lt]) : 0.f;
        float hdB = wB1 ? __ldcg(&g_h[(size_t)prB.y * HH + lt]) : 0.f;
        float cdB = wB1 ? __ldcg(&g_c[(size_t)prB.y * HH + lt]) : 0.f;
        sHpA[lt] = make_float2(hsA, hdA);
        sSDA[lt] = make_float2(hsA + hdA, hsA - hdA);
        sHpB[lt] = make_float2(hsB, hdB);
        sSDB[lt] = make_float2(hsB + hdB, hsB - hdB);
        if (lt < EADIM) {
            sCommA[lt] = eattr[eA * EADIM + lt];
            sCommB[lt] = eattr[eB * EADIM + lt];
        } else {
            int i = lt - EADIM;
            sCommA[lt] = cosf(__ldg(&etime[eA]) * cx.stw[i] + cx.stb[i]);
            sCommB[lt] = cosf(__ldg(&etime[eB]) * cx.stw[i] + cx.stb[i]);
        }
        bar_group(g);

        // ---- gemm1 for both events, weights loaded once ----
        float uA = 0.f, vA = 0.f, uB = 0.f, vB = 0.f;
        float acA = cx.sbmsg[lt], acB = acA;
        #pragma unroll 8
        for (int k = 0; k < 64; k++) {
            float2 w  = cx.sWpm[k * 64 + lt];
            float2 a = sSDA[k];
            float2 b = sSDB[k];
            uA = fmaf(a.x, w.x, uA); vA = fmaf(a.y, w.y, vA);
            uB = fmaf(b.x, w.x, uB); vB = fmaf(b.y, w.y, vB);
        }
        const float2* cmA = (const float2*)sCommA;
        const float2* cmB = (const float2*)sCommB;
        #pragma unroll 8
        for (int k2 = 0; k2 < 32; k2++) {
            float2 w = cx.sWc[k2 * 64 + lt];
            float2 a = cmA[k2];
            float2 b = cmB[k2];
            acA = fmaf(a.x, w.x, acA); acA = fmaf(a.y, w.y, acA);
            acB = fmaf(b.x, w.x, acB); acB = fmaf(b.y, w.y, acB);
        }
        sMpA[lt] = make_float2(fmaxf(acA + 0.5f * (uA - vA), 0.f),
                               fmaxf(acA + 0.5f * (uA + vA), 0.f));
        sMpB[lt] = make_float2(fmaxf(acB + 0.5f * (uB - vB), 0.f),
                               fmaxf(acB + 0.5f * (uB + vB), 0.f));
        bar_group(g);

        // ---- gemm2 for both events, weights loaded once (16 accumulators) ----
        float bl0 = cx.sblstm[lt],       bl1 = cx.sblstm[lt + 64];
        float bl2 = cx.sblstm[lt + 128], bl3 = cx.sblstm[lt + 192];
        float aA00 = bl0, aA01 = bl1, aA02 = bl2, aA03 = bl3;
        float aA10 = bl0, aA11 = bl1, aA12 = bl2, aA13 = bl3;
        float aB00 = bl0, aB01 = bl1, aB02 = bl2, aB03 = bl3;
        float aB10 = bl0, aB11 = bl1, aB12 = bl2, aB13 = bl3;
        #pragma unroll 4
        for (int k = 0; k < 64; k++) {
            float4 wi = *(const float4*)&cx.sWihP[(k * 64 + lt) * 4];
            float4 wh = *(const float4*)&cx.sWhhP[(k * 64 + lt) * 4];
            float2 mA = sMpA[k]; float2 hA = sHpA[k];
            float2 mB = sMpB[k]; float2 hB = sHpB[k];
            aA00 = fmaf(mA.x, wi.x, aA00); aA01 = fmaf(mA.x, wi.y, aA01);
            aA02 = fmaf(mA.x, wi.z, aA02); aA03 = fmaf(mA.x, wi.w, aA03);
            aA10 = fmaf(mA.y, wi.x, aA10); aA11 = fmaf(mA.y, wi.y, aA11);
            aA12 = fmaf(mA.y, wi.z, aA12); aA13 = fmaf(mA.y, wi.w, aA13);
            aA00 = fmaf(hA.x, wh.x, aA00); aA01 = fmaf(hA.x, wh.y, aA01);
            aA02 = fmaf(hA.x, wh.z, aA02); aA03 = fmaf(hA.x, wh.w, aA03);
            aA10 = fmaf(hA.y, wh.x, aA10); aA11 = fmaf(hA.y, wh.y, aA11);
            aA12 = fmaf(hA.y, wh.z, aA12); aA13 = fmaf(hA.y, wh.w, aA13);
            aB00 = fmaf(mB.x, wi.x, aB00); aB01 = fmaf(mB.x, wi.y, aB01);
            aB02 = fmaf(mB.x, wi.z, aB02); aB03 = fmaf(mB.x, wi.w, aB03);
            aB10 = fmaf(mB.y, wi.x, aB10); aB11 = fmaf(mB.y, wi.y, aB11);
            aB12 = fmaf(mB.y, wi.z, aB12); aB13 = fmaf(mB.y, wi.w, aB13);
            aB00 = fmaf(hB.x, wh.x, aB00); aB01 = fmaf(hB.x, wh.y, aB01);
            aB02 = fmaf(hB.x, wh.z, aB02); aB03 = fmaf(hB.x, wh.w, aB03);
            aB10 = fmaf(hB.y, wh.x, aB10); aB11 = fmaf(hB.y, wh.y, aB11);
            aB12 = fmaf(hB.y, wh.z, aB12); aB13 = fmaf(hB.y, wh.w, aB13);
        }

        // ---- elementwise + stores (dst row wins on per-event self-loop) ----
        bool slA = (prA.x == prA.y), slB = (prB.x == prB.y);
        {
            float cn = sigf(aA11) * cdA + sigf(aA10) * tanhx(aA12);
            float hn = sigf(aA13) * tanhx(cn);
            __stcg(&g_h[(size_t)prA.y * HH + lt], hn);
            __stcg(&g_c[(size_t)prA.y * HH + lt], cn);
        }
        if (!slA) {
            float cn = sigf(aA01) * csA + sigf(aA00) * tanhx(aA02);
            float hn = sigf(aA03) * tanhx(cn);
            __stcg(&g_h[(size_t)prA.x * HH + lt], hn);
            __stcg(&g_c[(size_t)prA.x * HH + lt], cn);
        }
        {
            float cn = sigf(aB11) * cdB + sigf(aB10) * tanhx(aB12);
            float hn = sigf(aB13) * tanhx(cn);
            __stcg(&g_h[(size_t)prB.y * HH + lt], hn);
            __stcg(&g_c[(size_t)prB.y * HH + lt], cn);
        }
        if (!slB) {
            float cn = sigf(aB01) * csB + sigf(aB00) * tanhx(aB02);
            float hn = sigf(aB03) * tanhx(cn);
            __stcg(&g_h[(size_t)prB.x * HH + lt], hn);
            __stcg(&g_c[(size_t)prB.x * HH + lt], cn);
        }
        bar_group(g);

        if (lt == 0) {
            __threadfence();
            if (slA) st_rel(&g_done[prA.x], s0A + 2);
            else { st_rel(&g_done[prA.x], s0A + 1); st_rel(&g_done[prA.y], s1A + 1); }
            if (slB) st_rel(&g_done[prB.x], s0B + 2);
            else { st_rel(&g_done[prB.x], s0B + 1); st_rel(&g_done[prB.y], s1B + 1); }
        }
        bar_group(g);
    }
}

// ---------------- kernel 3: epilogue — R9 config (256 blk × 256 thr) -------
// dyn smem layout (floats): sWf[KZ*AA] | sbf[64] | sCat[8][4][KZ]
#define EP_O_WF   0
#define EP_O_BF   (KZ * AA)                 // 9600
#define EP_O_CAT  (EP_O_BF + 64)            // 9664
#define EP_SMEM_F (EP_O_CAT + 8 * 4 * KZ)   // 15808 floats = 63232 B

__global__ void __launch_bounds__(256) epilogue_kernel(const float* __restrict__ x,
                                                       const int* __restrict__ eidx,
                                                       float* __restrict__ out) {
    extern __shared__ float esm[];
    float* sWf = esm + EP_O_WF;
    float* sbf = esm + EP_O_BF;
    int t = threadIdx.x;
    for (int i = t; i < KZ * AA; i += 256) sWf[i] = g_Wf[i];
    if (t < AA) sbf[t] = g_bf[t];
    __syncthreads();
    int lane = t & 31, w = t >> 5;
    float* sc = esm + EP_O_CAT + w * 4 * KZ;
    int e0 = (blockIdx.x * 8 + w) * 4;        // 4 events per warp
    #pragma unroll
    for (int j = 0; j < 4; j++) {
        int d = eidx[EE + e0 + j];
        const float* hv = &g_h[(size_t)d * HH];
        const float* xv = &x[(size_t)d * DFEAT];
        #pragma unroll
        for (int q = 0; q < 6; q++) {
            int k = lane + q * 32;
            sc[j * KZ + k] = (k < HH) ? hv[k] : xv[k - HH];
        }
    }
    __syncwarp();
    bool hi = (lane < AA - 32);
    float b0 = sbf[lane], b1 = hi ? sbf[lane + 32] : 0.f;
    float a00 = b0, a01 = b1, a10 = b0, a11 = b1;
    float a20 = b0, a21 = b1, a30 = b0, a31 = b1;
    for (int k4 = 0; k4 < KZ; k4 += 4) {
        float4 v0 = *(const float4*)&sc[0 * KZ + k4];
        float4 v1 = *(const float4*)&sc[1 * KZ + k4];
        float4 v2 = *(const float4*)&sc[2 * KZ + k4];
        float4 v3 = *(const float4*)&sc[3 * KZ + k4];
        #pragma unroll
        for (int i = 0; i < 4; i++) {
            float wA = sWf[(k4 + i) * AA + lane];
            float wB = hi ? sWf[(k4 + i) * AA + lane + 32] : 0.f;
            float e0v = (&v0.x)[i], e1v = (&v1.x)[i];
            float e2v = (&v2.x)[i], e3v = (&v3.x)[i];
            a00 = fmaf(e0v, wA, a00); a01 = fmaf(e0v, wB, a01);
            a10 = fmaf(e1v, wA, a10); a11 = fmaf(e1v, wB, a11);
            a20 = fmaf(e2v, wA, a20); a21 = fmaf(e2v, wB, a21);
            a30 = fmaf(e3v, wA, a30); a31 = fmaf(e3v, wB, a31);
        }
    }
    out[(size_t)(e0 + 0) * AA + lane] = a00;
    out[(size_t)(e0 + 1) * AA + lane] = a10;
    out[(size_t)(e0 + 2) * AA + lane] = a20;
    out[(size_t)(e0 + 3) * AA + lane] = a30;
    if (hi) {
        out[(size_t)(e0 + 0) * AA + lane + 32] = a01;
        out[(size_t)(e0 + 1) * AA + lane + 32] = a11;
        out[(size_t)(e0 + 2) * AA + lane + 32] = a21;
        out[(size_t)(e0 + 3) * AA + lane + 32] = a31;
    }
}

// ---------------- launch ----------------
extern "C" void kernel_launch(void* const* d_in, const int* in_sizes, int n_in,
                              void* d_out, int out_size) {
    const float* x      = (const float*)d_in[0];
    const int*   eidx   = (const int*)  d_in[1];
    const float* eattr  = (const float*)d_in[2];
    const float* etime  = (const float*)d_in[3];
    const float* time_w = (const float*)d_in[4];
    const float* time_b = (const float*)d_in[5];
    const float* W_msg  = (const float*)d_in[6];
    const float* b_msg  = (const float*)d_in[7];
    const float* W_ih   = (const float*)d_in[8];
    const float* W_hh   = (const float*)d_in[9];
    const float* b_lstm = (const float*)d_in[10];
    const float* W_emb  = (const float*)d_in[11];
    const float* b_emb  = (const float*)d_in[12];
    const float* W_cls  = (const float*)d_in[13];
    const float* b_cls  = (const float*)d_in[14];
    float* out = (float*)d_out;

    cudaFuncSetAttribute(scan_kernel, cudaFuncAttributeMaxDynamicSharedMemorySize,
                         SCAN_SMEM_F * (int)sizeof(float));
    cudaFuncSetAttribute(epilogue_kernel, cudaFuncAttributeMaxDynamicSharedMemorySize,
                         EP_SMEM_F * (int)sizeof(float));

    misc_kernel<<<MISC_BLOCKS, 256>>>(W_emb, W_cls, b_emb, b_cls);
    scan_kernel<<<SCAN_BLOCKS, BDIM, SCAN_SMEM_F * sizeof(float)>>>(
        eidx, W_msg, b_msg, W_ih, W_hh, b_lstm, time_w, time_b, eattr, etime);
    epilogue_kernel<<<256, 256, EP_SMEM_F * sizeof(float)>>>(x, eidx, out);
}